// round 3
// baseline (speedup 1.0000x reference)
#include <cuda_runtime.h>
#include <cstdint>

// StateDecoder: out[b, r, c] = (x[b, c] >> r) & 1 as float32.
// B = 2048, C = 2048, R = 32. 16 MiB in, 512 MiB out -> write-bandwidth bound.
//
// R3: stage output tiles in SMEM and drain them with TMA 1-D bulk stores
// (cp.async.bulk.global.shared::cta), 16 KB contiguous per store, double
// buffered. Goal: long sequential DRAM write bursts from one TMA agent per
// SM instead of fine-grained interleaved STG streams from 16k warps.

#define BATCH 2048
#define NUM_CANDIDATES 2048
#define NUM_REPLICAS 32

#define R_TILE 2                              // r-rows per tile
#define TILE_FLOATS (R_TILE * NUM_CANDIDATES) // 4096 floats = 16 KB
#define NUM_TILES (NUM_REPLICAS / R_TILE)     // 16

__device__ __forceinline__ float4 bits_to_f4(int4 v, int r) {
    unsigned f0 = (0u - (((unsigned)v.x >> r) & 1u)) & 0x3F800000u;
    unsigned f1 = (0u - (((unsigned)v.y >> r) & 1u)) & 0x3F800000u;
    unsigned f2 = (0u - (((unsigned)v.z >> r) & 1u)) & 0x3F800000u;
    unsigned f3 = (0u - (((unsigned)v.w >> r) & 1u)) & 0x3F800000u;
    float4 f;
    f.x = __uint_as_float(f0);
    f.y = __uint_as_float(f1);
    f.z = __uint_as_float(f2);
    f.w = __uint_as_float(f3);
    return f;
}

__global__ __launch_bounds__(256) void state_decoder_kernel(
    const int4* __restrict__ x4,   // [B * C/4]
    float* __restrict__ out        // [B * R * C]
) {
    __shared__ float stile[2][R_TILE][NUM_CANDIDATES];  // 2 x 16 KB

    constexpr int C4 = NUM_CANDIDATES / 4;   // 512
    constexpr int HALF = C4 / 2;             // 256

    const int b = blockIdx.x;
    const int j = threadIdx.x;               // 0..255

    // Row input: thread j owns c-chunks j and j+HALF (c = j*4 and 1024+j*4).
    const int4 va = x4[(size_t)b * C4 + j];
    const int4 vb = x4[(size_t)b * C4 + j + HALF];

    float* const out_row = out + (size_t)b * (NUM_REPLICAS * NUM_CANDIDATES);

    #pragma unroll 1
    for (int t = 0; t < NUM_TILES; ++t) {
        const int buf = t & 1;

        // Before overwriting this buffer, ensure the bulk store issued two
        // tiles ago has finished READING it (<=1 group still pending).
        if (t >= 2) {
            if (threadIdx.x == 0) {
                asm volatile("cp.async.bulk.wait_group.read %0;" :: "n"(1) : "memory");
            }
            __syncthreads();
        }

        // Fill tile: r = R_TILE*t + rl
        #pragma unroll
        for (int rl = 0; rl < R_TILE; ++rl) {
            const int r = R_TILE * t + rl;
            float4 fa = bits_to_f4(va, r);
            float4 fb = bits_to_f4(vb, r);
            *reinterpret_cast<float4*>(&stile[buf][rl][j * 4])        = fa;
            *reinterpret_cast<float4*>(&stile[buf][rl][1024 + j * 4]) = fb;
        }
        __syncthreads();

        if (threadIdx.x == 0) {
            // Order generic-proxy STS before async-proxy TMA read.
            asm volatile("fence.proxy.async.shared::cta;" ::: "memory");
            uint32_t saddr = (uint32_t)__cvta_generic_to_shared(&stile[buf][0][0]);
            float* dst = out_row + (size_t)t * TILE_FLOATS;
            asm volatile(
                "cp.async.bulk.global.shared::cta.bulk_group [%0], [%1], %2;"
                :: "l"(dst), "r"(saddr), "n"(TILE_FLOATS * 4)
                : "memory");
            asm volatile("cp.async.bulk.commit_group;" ::: "memory");
        }
        __syncthreads();
    }

    // Drain all outstanding bulk stores before exit.
    if (threadIdx.x == 0) {
        asm volatile("cp.async.bulk.wait_group %0;" :: "n"(0) : "memory");
    }
}

extern "C" void kernel_launch(void* const* d_in, const int* in_sizes, int n_in,
                              void* d_out, int out_size) {
    const int4* x4 = (const int4*)d_in[0];
    float* out = (float*)d_out;

    state_decoder_kernel<<<BATCH, 256>>>(x4, out);
}